// round 1
// baseline (speedup 1.0000x reference)
#include <cuda_runtime.h>

#define NPTS    8192
#define BATCH   4
#define NPOINT  2048
#define NSAMPLE 32
#define CIN     67
#define COUT    128
#define KTOT    (CIN * NSAMPLE)   // 2144
#define R2      0.04f

// scratch: ball query neighbor indices (B, NPOINT, NSAMPLE)
__device__ int g_ball_idx[BATCH * NPOINT * NSAMPLE];

// ---------------------------------------------------------------------------
// Kernel 1: Furthest Point Sampling. One CTA (1024 thr) per batch.
// Points staged in SMEM; per-thread dist array (8 pts) in registers.
// Writes new_xyz directly into d_out[0 .. B*NPOINT*3).
// ---------------------------------------------------------------------------
__global__ void __launch_bounds__(1024, 1)
fps_kernel(const float* __restrict__ points, float* __restrict__ new_xyz)
{
    extern __shared__ float pts[];      // NPTS*3 floats
    __shared__ float redv[32];
    __shared__ int   redi[32];
    __shared__ int   s_best;

    const int b = blockIdx.x;
    const int t = threadIdx.x;
    const float* P = points + (size_t)b * NPTS * 3;

    for (int i = t; i < NPTS * 3; i += 1024) pts[i] = P[i];
    __syncthreads();

    const int PPT = NPTS / 1024;   // 8 points per thread, contiguous
    const int base = t * PPT;
    float px[8], py[8], pz[8], dist[8];
#pragma unroll
    for (int j = 0; j < PPT; j++) {
        px[j] = pts[(base + j) * 3 + 0];
        py[j] = pts[(base + j) * 3 + 1];
        pz[j] = pts[(base + j) * 3 + 2];
        dist[j] = 1e10f;
    }

    float lx = pts[0], ly = pts[1], lz = pts[2];
    if (t == 0) {
        float* o = new_xyz + (size_t)b * NPOINT * 3;
        o[0] = lx; o[1] = ly; o[2] = lz;
    }

    for (int iter = 1; iter < NPOINT; ++iter) {
        float bv = -1.0f; int bi = 0;
#pragma unroll
        for (int j = 0; j < PPT; j++) {
            // match JAX exactly: no fma contraction, (x2+y2)+z2 order
            float dx = __fadd_rn(px[j], -lx);
            float dy = __fadd_rn(py[j], -ly);
            float dz = __fadd_rn(pz[j], -lz);
            float d = __fadd_rn(__fadd_rn(__fmul_rn(dx, dx), __fmul_rn(dy, dy)),
                                __fmul_rn(dz, dz));
            float nd = fminf(dist[j], d);
            dist[j] = nd;
            if (nd > bv) { bv = nd; bi = base + j; }   // strict > => lowest idx
        }
        // warp-level argmax (lowest index on ties)
#pragma unroll
        for (int off = 16; off > 0; off >>= 1) {
            float ov = __shfl_down_sync(0xffffffffu, bv, off);
            int   oi = __shfl_down_sync(0xffffffffu, bi, off);
            if (ov > bv || (ov == bv && oi < bi)) { bv = ov; bi = oi; }
        }
        const int w = t >> 5;
        if ((t & 31) == 0) { redv[w] = bv; redi[w] = bi; }
        __syncthreads();
        if (w == 0) {
            bv = redv[t & 31]; bi = redi[t & 31];
#pragma unroll
            for (int off = 16; off > 0; off >>= 1) {
                float ov = __shfl_down_sync(0xffffffffu, bv, off);
                int   oi = __shfl_down_sync(0xffffffffu, bi, off);
                if (ov > bv || (ov == bv && oi < bi)) { bv = ov; bi = oi; }
            }
            if (t == 0) s_best = bi;
        }
        __syncthreads();
        const int best = s_best;
        lx = pts[best * 3 + 0];
        ly = pts[best * 3 + 1];
        lz = pts[best * 3 + 2];
        if (t == 0) {
            float* o = new_xyz + ((size_t)b * NPOINT + iter) * 3;
            o[0] = lx; o[1] = ly; o[2] = lz;
        }
    }
}

// ---------------------------------------------------------------------------
// Kernel 2: ball query. One warp per center. Collects the first NSAMPLE
// point indices (ascending) with d2 < R2, padded with the first found index.
// ---------------------------------------------------------------------------
__global__ void __launch_bounds__(256)
ball_kernel(const float* __restrict__ points, const float* __restrict__ new_xyz,
            int* __restrict__ out_idx)
{
    const int gw = (blockIdx.x * blockDim.x + threadIdx.x) >> 5;
    const int lane = threadIdx.x & 31;
    if (gw >= BATCH * NPOINT) return;
    const int b = gw / NPOINT;
    const float* P = points + (size_t)b * NPTS * 3;

    const float cx = new_xyz[gw * 3 + 0];
    const float cy = new_xyz[gw * 3 + 1];
    const float cz = new_xyz[gw * 3 + 2];
    int* row = out_idx + (size_t)gw * NSAMPLE;

    int filled = 0;
    int first = 0;
    for (int basei = 0; basei < NPTS; basei += 32) {
        const int i = basei + lane;
        float x = P[i * 3 + 0], y = P[i * 3 + 1], z = P[i * 3 + 2];
        float dx = __fadd_rn(x, -cx);
        float dy = __fadd_rn(y, -cy);
        float dz = __fadd_rn(z, -cz);
        float d2 = __fadd_rn(__fadd_rn(__fmul_rn(dx, dx), __fmul_rn(dy, dy)),
                             __fmul_rn(dz, dz));
        unsigned m = __ballot_sync(0xffffffffu, d2 < R2);
        if (filled == 0 && m) first = basei + __ffs(m) - 1;
        if (d2 < R2) {
            int pos = filled + __popc(m & ((1u << lane) - 1));
            if (pos < NSAMPLE) row[pos] = i;
        }
        filled += __popc(m);
        if (filled >= NSAMPLE) break;
    }
    for (int j = filled + lane; j < NSAMPLE; j += 32) row[j] = first;
}

// ---------------------------------------------------------------------------
// Kernel 3: fused gather + pointwise conv.
// conv[b,p,o] = sum_{s,c} g[b,p,s,c] * w[o,c,s], k = c*32+s (matches W layout).
// Block = 64 points x 128 outputs, K streamed in 4-channel (128-k) chunks
// through SMEM. Thread: og = t%32 -> o in {og, og+32, og+64, og+96};
// pg = t/32 -> 8 points. 32 accumulators/thread.
// ---------------------------------------------------------------------------
#define PT 64

__global__ void __launch_bounds__(256, 1)
conv_kernel(const float* __restrict__ points,
            const float* __restrict__ features,
            const float* __restrict__ weight,
            const float* __restrict__ new_xyz,
            const int* __restrict__ ball_idx,
            float* __restrict__ conv_out)
{
    extern __shared__ char smraw[];
    float* s_g   = (float*)smraw;              // [64][128]
    float* s_w   = s_g + PT * 128;             // [128][129] padded
    int*   s_idx = (int*)(s_w + COUT * 129);   // [64][32]
    float* s_ctr = (float*)(s_idx + PT * NSAMPLE); // [64][3]

    const int t = threadIdx.x;
    const int b  = blockIdx.x >> 5;            // NPOINT/PT = 32 tiles per batch
    const int p0 = (blockIdx.x & 31) * PT;
    const float* P = points   + (size_t)b * NPTS * 3;
    const float* F = features + (size_t)b * NPTS * 64;

    for (int i = t; i < PT * NSAMPLE; i += 256)
        s_idx[i] = ball_idx[((size_t)b * NPOINT + p0) * NSAMPLE + i];
    for (int i = t; i < PT * 3; i += 256)
        s_ctr[i] = new_xyz[((size_t)b * NPOINT + p0) * 3 + i];
    __syncthreads();

    int myidx[8];
#pragma unroll
    for (int q = 0; q < 8; q++) myidx[q] = s_idx[q * 256 + t];

    const int og = t & 31;
    const int pg = t >> 5;
    float acc[8][4];
#pragma unroll
    for (int i = 0; i < 8; i++)
#pragma unroll
        for (int j = 0; j < 4; j++) acc[i][j] = 0.0f;

    for (int chunk = 0; chunk < 17; chunk++) {
        const int c0 = chunk * 4;
        const int nc = (chunk == 16) ? 3 : 4;
        __syncthreads();   // previous compute done before overwrite

        // stage g tile: 64p x 32s pairs, transposed to [p][ci*32 + s]
#pragma unroll
        for (int q = 0; q < 8; q++) {
            const int pr = q * 256 + t;
            const int p = pr >> 5, s = pr & 31;
            const int idx = myidx[q];
#pragma unroll
            for (int ci = 0; ci < 4; ci++) {
                const int c = c0 + ci;
                if (c >= CIN) break;
                float v;
                if (c < 3) v = P[idx * 3 + c] - s_ctr[p * 3 + c];
                else       v = F[idx * 64 + (c - 3)];
                s_g[p * 128 + ci * 32 + s] = v;
            }
        }
        // stage W tile: 128 o x up to 128 k, vectorized along k
        const int kend = nc * 32;
#pragma unroll
        for (int q = 0; q < 16; q++) {
            const int task = q * 256 + t;
            const int o = task >> 5;
            const int k4 = (task & 31) * 4;
            if (k4 < kend) {
                float4 wv = *(const float4*)(weight + (size_t)o * KTOT + c0 * 32 + k4);
                s_w[o * 129 + k4 + 0] = wv.x;
                s_w[o * 129 + k4 + 1] = wv.y;
                s_w[o * 129 + k4 + 2] = wv.z;
                s_w[o * 129 + k4 + 3] = wv.w;
            }
        }
        __syncthreads();

#pragma unroll 4
        for (int kk = 0; kk < kend; kk++) {
            const float w0 = s_w[(og +  0) * 129 + kk];
            const float w1 = s_w[(og + 32) * 129 + kk];
            const float w2 = s_w[(og + 64) * 129 + kk];
            const float w3 = s_w[(og + 96) * 129 + kk];
#pragma unroll
            for (int i = 0; i < 8; i++) {
                const float g = s_g[(pg * 8 + i) * 128 + kk];
                acc[i][0] = fmaf(g, w0, acc[i][0]);
                acc[i][1] = fmaf(g, w1, acc[i][1]);
                acc[i][2] = fmaf(g, w2, acc[i][2]);
                acc[i][3] = fmaf(g, w3, acc[i][3]);
            }
        }
    }

#pragma unroll
    for (int i = 0; i < 8; i++) {
        const int p = p0 + pg * 8 + i;
        float* dst = conv_out + ((size_t)b * NPOINT + p) * COUT;
        dst[og +  0] = acc[i][0];
        dst[og + 32] = acc[i][1];
        dst[og + 64] = acc[i][2];
        dst[og + 96] = acc[i][3];
    }
}

// ---------------------------------------------------------------------------

extern "C" void kernel_launch(void* const* d_in, const int* in_sizes, int n_in,
                              void* d_out, int out_size)
{
    const float* points   = (const float*)d_in[0];
    const float* features = (const float*)d_in[1];
    const float* weight   = (const float*)d_in[2];
    float* out = (float*)d_out;
    float* new_xyz = out;                            // B*NPOINT*3
    float* conv    = out + BATCH * NPOINT * 3;       // B*NPOINT*COUT

    const int fps_smem  = NPTS * 3 * sizeof(float);                       // 96 KB
    const int conv_smem = (PT * 128 + COUT * 129 + PT * 3) * sizeof(float)
                        + PT * NSAMPLE * sizeof(int);                     // ~106 KB

    cudaFuncSetAttribute(fps_kernel,  cudaFuncAttributeMaxDynamicSharedMemorySize, fps_smem);
    cudaFuncSetAttribute(conv_kernel, cudaFuncAttributeMaxDynamicSharedMemorySize, conv_smem);

    int* ball_ptr = nullptr;
    cudaGetSymbolAddress((void**)&ball_ptr, g_ball_idx);

    fps_kernel<<<BATCH, 1024, fps_smem>>>(points, new_xyz);
    ball_kernel<<<(BATCH * NPOINT) / 8, 256>>>(points, new_xyz, ball_ptr);
    conv_kernel<<<BATCH * (NPOINT / PT), 256, conv_smem>>>(
        points, features, weight, new_xyz, ball_ptr, conv);
}

// round 2
// speedup vs baseline: 1.7516x; 1.7516x over previous
#include <cuda_runtime.h>

#define NPTS    8192
#define BATCH   4
#define NPOINT  2048
#define NSAMPLE 32
#define CIN     67
#define COUT    128
#define KTOT    (CIN * NSAMPLE)   // 2144
#define R2      0.04f

// scratch: ball query neighbor indices (B, NPOINT, NSAMPLE)
__device__ int g_ball_idx[BATCH * NPOINT * NSAMPLE];

// ---------------------------------------------------------------------------
// packed f32x2 helpers (sm_103a)
// ---------------------------------------------------------------------------
__device__ __forceinline__ unsigned long long f2pk(float lo, float hi) {
    unsigned long long r;
    asm("mov.b64 %0, {%1, %2};" : "=l"(r) : "f"(lo), "f"(hi));
    return r;
}
__device__ __forceinline__ void f2unpk(unsigned long long v, float& lo, float& hi) {
    asm("mov.b64 {%0, %1}, %2;" : "=f"(lo), "=f"(hi) : "l"(v));
}
__device__ __forceinline__ unsigned long long f2add(unsigned long long a, unsigned long long b) {
    unsigned long long r;
    asm("add.rn.f32x2 %0, %1, %2;" : "=l"(r) : "l"(a), "l"(b));
    return r;
}
__device__ __forceinline__ unsigned long long f2mul(unsigned long long a, unsigned long long b) {
    unsigned long long r;
    asm("mul.rn.f32x2 %0, %1, %2;" : "=l"(r) : "l"(a), "l"(b));
    return r;
}

// ---------------------------------------------------------------------------
// Kernel 1: Furthest Point Sampling. One CTA (512 thr) per batch.
// Packed f32x2 distance math (bit-identical to scalar mul/add order used by
// the reference-matching R1 kernel), redux.sync value reduction, index
// recovery by winner-only rescan + atomicMin (lowest index on ties).
// ---------------------------------------------------------------------------
#define FPS_T   512
#define PPT     (NPTS / FPS_T)    // 16 points per thread
#define NPAIR   (PPT / 2)         // 8 packed pairs

__global__ void __launch_bounds__(FPS_T, 1)
fps_kernel(const float* __restrict__ points, float* __restrict__ new_xyz)
{
    extern __shared__ float pts[];           // NPTS*3 floats
    __shared__ unsigned redv[FPS_T / 32];    // per-warp max bits
    __shared__ unsigned s_vmax;
    __shared__ int      s_best[2];           // parity double-buffered

    const int b = blockIdx.x;
    const int t = threadIdx.x;
    const int lane = t & 31;
    const int w = t >> 5;
    const float* P = points + (size_t)b * NPTS * 3;

    for (int i = t; i < NPTS * 3; i += FPS_T) pts[i] = P[i];
    if (t == 0) { s_best[0] = 0x7fffffff; s_best[1] = 0x7fffffff; }
    __syncthreads();

    const int base = t * PPT;
    unsigned long long px2[NPAIR], py2[NPAIR], pz2[NPAIR];
    float dist[PPT];
#pragma unroll
    for (int j = 0; j < NPAIR; j++) {
        const int p0 = base + 2 * j;
        px2[j] = f2pk(pts[p0 * 3 + 0], pts[p0 * 3 + 3]);
        py2[j] = f2pk(pts[p0 * 3 + 1], pts[p0 * 3 + 4]);
        pz2[j] = f2pk(pts[p0 * 3 + 2], pts[p0 * 3 + 5]);
    }
#pragma unroll
    for (int j = 0; j < PPT; j++) dist[j] = 1e10f;

    float lx = pts[0], ly = pts[1], lz = pts[2];
    if (t == 0) {
        float* o = new_xyz + (size_t)b * NPOINT * 3;
        o[0] = lx; o[1] = ly; o[2] = lz;
    }

    for (int iter = 1; iter < NPOINT; ++iter) {
        const unsigned long long nx2 = f2pk(-lx, -lx);
        const unsigned long long ny2 = f2pk(-ly, -ly);
        const unsigned long long nz2 = f2pk(-lz, -lz);

        float bv = -1.0f;
#pragma unroll
        for (int j = 0; j < NPAIR; j++) {
            // identical arithmetic to scalar: (dx*dx + dy*dy) + dz*dz, rn
            unsigned long long dx = f2add(px2[j], nx2);
            unsigned long long dy = f2add(py2[j], ny2);
            unsigned long long dz = f2add(pz2[j], nz2);
            unsigned long long d2 = f2add(f2add(f2mul(dx, dx), f2mul(dy, dy)),
                                          f2mul(dz, dz));
            float d0, d1;
            f2unpk(d2, d0, d1);
            float n0 = fminf(dist[2 * j + 0], d0);
            float n1 = fminf(dist[2 * j + 1], d1);
            dist[2 * j + 0] = n0;
            dist[2 * j + 1] = n1;
            bv = fmaxf(bv, fmaxf(n0, n1));
        }

        // value-only reduction (dist >= 0 -> uint order == float order)
        const unsigned bb = __float_as_uint(bv);
        const unsigned wm = __reduce_max_sync(0xffffffffu, bb);
        if (lane == 0) redv[w] = wm;
        __syncthreads();                               // bar 1

        const int par = iter & 1;
        if (w == 0) {
            unsigned v = (lane < FPS_T / 32) ? redv[lane] : 0u;
            unsigned gm = __reduce_max_sync(0xffffffffu, v);
            if (lane == 0) {
                s_vmax = gm;
                s_best[par ^ 1] = 0x7fffffff;          // reset next iter's slot
            }
        }
        __syncthreads();                               // bar 2

        const unsigned vmax = s_vmax;
        if (bb == vmax) {
            int idx = 0x7fffffff;
#pragma unroll
            for (int j = PPT - 1; j >= 0; j--)
                if (__float_as_uint(dist[j]) == vmax) idx = base + j;
            atomicMin(&s_best[par], idx);
        }
        __syncthreads();                               // bar 3

        const int best = s_best[par];
        lx = pts[best * 3 + 0];
        ly = pts[best * 3 + 1];
        lz = pts[best * 3 + 2];
        if (t == 0) {
            float* o = new_xyz + ((size_t)b * NPOINT + iter) * 3;
            o[0] = lx; o[1] = ly; o[2] = lz;
        }
    }
}

// ---------------------------------------------------------------------------
// Kernel 2: ball query. One warp per center. Collects the first NSAMPLE
// point indices (ascending) with d2 < R2, padded with the first found index.
// ---------------------------------------------------------------------------
__global__ void __launch_bounds__(256)
ball_kernel(const float* __restrict__ points, const float* __restrict__ new_xyz,
            int* __restrict__ out_idx)
{
    const int gw = (blockIdx.x * blockDim.x + threadIdx.x) >> 5;
    const int lane = threadIdx.x & 31;
    if (gw >= BATCH * NPOINT) return;
    const int b = gw / NPOINT;
    const float* P = points + (size_t)b * NPTS * 3;

    const float cx = new_xyz[gw * 3 + 0];
    const float cy = new_xyz[gw * 3 + 1];
    const float cz = new_xyz[gw * 3 + 2];
    int* row = out_idx + (size_t)gw * NSAMPLE;

    int filled = 0;
    int first = 0;
    for (int basei = 0; basei < NPTS; basei += 32) {
        const int i = basei + lane;
        float x = P[i * 3 + 0], y = P[i * 3 + 1], z = P[i * 3 + 2];
        float dx = __fadd_rn(x, -cx);
        float dy = __fadd_rn(y, -cy);
        float dz = __fadd_rn(z, -cz);
        float d2 = __fadd_rn(__fadd_rn(__fmul_rn(dx, dx), __fmul_rn(dy, dy)),
                             __fmul_rn(dz, dz));
        unsigned m = __ballot_sync(0xffffffffu, d2 < R2);
        if (filled == 0 && m) first = basei + __ffs(m) - 1;
        if (d2 < R2) {
            int pos = filled + __popc(m & ((1u << lane) - 1));
            if (pos < NSAMPLE) row[pos] = i;
        }
        filled += __popc(m);
        if (filled >= NSAMPLE) break;
    }
    for (int j = filled + lane; j < NSAMPLE; j += 32) row[j] = first;
}

// ---------------------------------------------------------------------------
// Kernel 3: fused gather + pointwise conv.
// conv[b,p,o] = sum_{s,c} g[b,p,s,c] * w[o,c,s], k = c*32+s (matches W layout).
// Block = 64 points x 128 outputs, K streamed in 4-channel (128-k) chunks
// through SMEM. Thread: og = t%32 -> o in {og, og+32, og+64, og+96};
// pg = t/32 -> 8 points. 32 accumulators/thread.
// ---------------------------------------------------------------------------
#define PT 64

__global__ void __launch_bounds__(256, 1)
conv_kernel(const float* __restrict__ points,
            const float* __restrict__ features,
            const float* __restrict__ weight,
            const float* __restrict__ new_xyz,
            const int* __restrict__ ball_idx,
            float* __restrict__ conv_out)
{
    extern __shared__ char smraw[];
    float* s_g   = (float*)smraw;              // [64][128]
    float* s_w   = s_g + PT * 128;             // [128][129] padded
    int*   s_idx = (int*)(s_w + COUT * 129);   // [64][32]
    float* s_ctr = (float*)(s_idx + PT * NSAMPLE); // [64][3]

    const int t = threadIdx.x;
    const int b  = blockIdx.x >> 5;            // NPOINT/PT = 32 tiles per batch
    const int p0 = (blockIdx.x & 31) * PT;
    const float* P = points   + (size_t)b * NPTS * 3;
    const float* F = features + (size_t)b * NPTS * 64;

    for (int i = t; i < PT * NSAMPLE; i += 256)
        s_idx[i] = ball_idx[((size_t)b * NPOINT + p0) * NSAMPLE + i];
    for (int i = t; i < PT * 3; i += 256)
        s_ctr[i] = new_xyz[((size_t)b * NPOINT + p0) * 3 + i];
    __syncthreads();

    int myidx[8];
#pragma unroll
    for (int q = 0; q < 8; q++) myidx[q] = s_idx[q * 256 + t];

    const int og = t & 31;
    const int pg = t >> 5;
    float acc[8][4];
#pragma unroll
    for (int i = 0; i < 8; i++)
#pragma unroll
        for (int j = 0; j < 4; j++) acc[i][j] = 0.0f;

    for (int chunk = 0; chunk < 17; chunk++) {
        const int c0 = chunk * 4;
        const int nc = (chunk == 16) ? 3 : 4;
        __syncthreads();   // previous compute done before overwrite

        // stage g tile: 64p x 32s pairs, transposed to [p][ci*32 + s]
#pragma unroll
        for (int q = 0; q < 8; q++) {
            const int pr = q * 256 + t;
            const int p = pr >> 5, s = pr & 31;
            const int idx = myidx[q];
#pragma unroll
            for (int ci = 0; ci < 4; ci++) {
                const int c = c0 + ci;
                if (c >= CIN) break;
                float v;
                if (c < 3) v = P[idx * 3 + c] - s_ctr[p * 3 + c];
                else       v = F[idx * 64 + (c - 3)];
                s_g[p * 128 + ci * 32 + s] = v;
            }
        }
        // stage W tile: 128 o x up to 128 k, vectorized along k
        const int kend = nc * 32;
#pragma unroll
        for (int q = 0; q < 16; q++) {
            const int task = q * 256 + t;
            const int o = task >> 5;
            const int k4 = (task & 31) * 4;
            if (k4 < kend) {
                float4 wv = *(const float4*)(weight + (size_t)o * KTOT + c0 * 32 + k4);
                s_w[o * 129 + k4 + 0] = wv.x;
                s_w[o * 129 + k4 + 1] = wv.y;
                s_w[o * 129 + k4 + 2] = wv.z;
                s_w[o * 129 + k4 + 3] = wv.w;
            }
        }
        __syncthreads();

#pragma unroll 4
        for (int kk = 0; kk < kend; kk++) {
            const float w0 = s_w[(og +  0) * 129 + kk];
            const float w1 = s_w[(og + 32) * 129 + kk];
            const float w2 = s_w[(og + 64) * 129 + kk];
            const float w3 = s_w[(og + 96) * 129 + kk];
#pragma unroll
            for (int i = 0; i < 8; i++) {
                const float g = s_g[(pg * 8 + i) * 128 + kk];
                acc[i][0] = fmaf(g, w0, acc[i][0]);
                acc[i][1] = fmaf(g, w1, acc[i][1]);
                acc[i][2] = fmaf(g, w2, acc[i][2]);
                acc[i][3] = fmaf(g, w3, acc[i][3]);
            }
        }
    }

#pragma unroll
    for (int i = 0; i < 8; i++) {
        const int p = p0 + pg * 8 + i;
        float* dst = conv_out + ((size_t)b * NPOINT + p) * COUT;
        dst[og +  0] = acc[i][0];
        dst[og + 32] = acc[i][1];
        dst[og + 64] = acc[i][2];
        dst[og + 96] = acc[i][3];
    }
}

// ---------------------------------------------------------------------------

extern "C" void kernel_launch(void* const* d_in, const int* in_sizes, int n_in,
                              void* d_out, int out_size)
{
    const float* points   = (const float*)d_in[0];
    const float* features = (const float*)d_in[1];
    const float* weight   = (const float*)d_in[2];
    float* out = (float*)d_out;
    float* new_xyz = out;                            // B*NPOINT*3
    float* conv    = out + BATCH * NPOINT * 3;       // B*NPOINT*COUT

    const int fps_smem  = NPTS * 3 * sizeof(float);                       // 96 KB
    const int conv_smem = (PT * 128 + COUT * 129 + PT * 3) * sizeof(float)
                        + PT * NSAMPLE * sizeof(int);                     // ~106 KB

    cudaFuncSetAttribute(fps_kernel,  cudaFuncAttributeMaxDynamicSharedMemorySize, fps_smem);
    cudaFuncSetAttribute(conv_kernel, cudaFuncAttributeMaxDynamicSharedMemorySize, conv_smem);

    int* ball_ptr = nullptr;
    cudaGetSymbolAddress((void**)&ball_ptr, g_ball_idx);

    fps_kernel<<<BATCH, FPS_T, fps_smem>>>(points, new_xyz);
    ball_kernel<<<(BATCH * NPOINT) / 8, 256>>>(points, new_xyz, ball_ptr);
    conv_kernel<<<BATCH * (NPOINT / PT), 256, conv_smem>>>(
        points, features, weight, new_xyz, ball_ptr, conv);
}

// round 3
// speedup vs baseline: 1.7868x; 1.0201x over previous
#include <cuda_runtime.h>

#define NPTS    8192
#define BATCH   4
#define NPOINT  2048
#define NSAMPLE 32
#define CIN     67
#define COUT    128
#define KTOT    (CIN * NSAMPLE)   // 2144
#define R2      0.04f

// scratch: ball query neighbor indices (B, NPOINT, NSAMPLE)
__device__ int g_ball_idx[BATCH * NPOINT * NSAMPLE];

// ---------------------------------------------------------------------------
// packed f32x2 helpers (sm_103a)
// ---------------------------------------------------------------------------
__device__ __forceinline__ unsigned long long f2pk(float lo, float hi) {
    unsigned long long r;
    asm("mov.b64 %0, {%1, %2};" : "=l"(r) : "f"(lo), "f"(hi));
    return r;
}
__device__ __forceinline__ void f2unpk(unsigned long long v, float& lo, float& hi) {
    asm("mov.b64 {%0, %1}, %2;" : "=f"(lo), "=f"(hi) : "l"(v));
}
__device__ __forceinline__ unsigned long long f2add(unsigned long long a, unsigned long long b) {
    unsigned long long r;
    asm("add.rn.f32x2 %0, %1, %2;" : "=l"(r) : "l"(a), "l"(b));
    return r;
}
__device__ __forceinline__ unsigned long long f2mul(unsigned long long a, unsigned long long b) {
    unsigned long long r;
    asm("mul.rn.f32x2 %0, %1, %2;" : "=l"(r) : "l"(a), "l"(b));
    return r;
}

// ---------------------------------------------------------------------------
// Kernel 1: Furthest Point Sampling. One CTA (512 thr) per batch.
// Packed f32x2 distance math (bit-identical rounding/order vs reference).
// Single-barrier reduction: per-warp (max value, lowest index) via redux +
// winner rescan, packed 64-bit exchange through smem (parity double-buffered),
// then every warp independently reduces the 16 warp results.
// ---------------------------------------------------------------------------
#define FPS_T   512
#define PPT     (NPTS / FPS_T)    // 16 points per thread
#define NPAIR   (PPT / 2)         // 8 packed pairs

__global__ void __launch_bounds__(FPS_T, 1)
fps_kernel(const float* __restrict__ points, float* __restrict__ new_xyz)
{
    extern __shared__ float pts[];                     // NPTS*3 floats
    __shared__ unsigned long long redw[2][FPS_T / 32]; // parity double-buffer

    const int b = blockIdx.x;
    const int t = threadIdx.x;
    const int lane = t & 31;
    const int w = t >> 5;
    const float* P = points + (size_t)b * NPTS * 3;

    for (int i = t; i < NPTS * 3; i += FPS_T) pts[i] = P[i];
    __syncthreads();

    const int base = t * PPT;
    unsigned long long px2[NPAIR], py2[NPAIR], pz2[NPAIR];
    float dist[PPT];
#pragma unroll
    for (int j = 0; j < NPAIR; j++) {
        const int p0 = base + 2 * j;
        px2[j] = f2pk(pts[p0 * 3 + 0], pts[p0 * 3 + 3]);
        py2[j] = f2pk(pts[p0 * 3 + 1], pts[p0 * 3 + 4]);
        pz2[j] = f2pk(pts[p0 * 3 + 2], pts[p0 * 3 + 5]);
    }
#pragma unroll
    for (int j = 0; j < PPT; j++) dist[j] = 1e10f;

    float lx = pts[0], ly = pts[1], lz = pts[2];
    if (t == 0) {
        float* o = new_xyz + (size_t)b * NPOINT * 3;
        o[0] = lx; o[1] = ly; o[2] = lz;
    }

    for (int iter = 1; iter < NPOINT; ++iter) {
        const int par = iter & 1;
        const unsigned long long nx2 = f2pk(-lx, -lx);
        const unsigned long long ny2 = f2pk(-ly, -ly);
        const unsigned long long nz2 = f2pk(-lz, -lz);

        float bv = -1.0f;
#pragma unroll
        for (int j = 0; j < NPAIR; j++) {
            // identical arithmetic to reference: (dx*dx + dy*dy) + dz*dz, rn
            unsigned long long dx = f2add(px2[j], nx2);
            unsigned long long dy = f2add(py2[j], ny2);
            unsigned long long dz = f2add(pz2[j], nz2);
            unsigned long long d2 = f2add(f2add(f2mul(dx, dx), f2mul(dy, dy)),
                                          f2mul(dz, dz));
            float d0, d1;
            f2unpk(d2, d0, d1);
            float n0 = fminf(dist[2 * j + 0], d0);
            float n1 = fminf(dist[2 * j + 1], d1);
            dist[2 * j + 0] = n0;
            dist[2 * j + 1] = n1;
            bv = fmaxf(bv, fmaxf(n0, n1));
        }

        // warp max value (dist >= 0 -> uint order == float order)
        const unsigned bb = __float_as_uint(bv);
        const unsigned wm = __reduce_max_sync(0xffffffffu, bb);

        // winner lane(s): lowest local index whose dist bits == wm
        unsigned li = 0x7fffffffu;
        if (bb == wm) {
#pragma unroll
            for (int j = PPT - 1; j >= 0; j--)
                if (__float_as_uint(dist[j]) == wm) li = base + j;
        }
        const unsigned wi = __reduce_min_sync(0xffffffffu, li);
        if (lane == 0)
            redw[par][w] = ((unsigned long long)wm << 32) | wi;
        __syncthreads();                               // the ONLY barrier

        // every warp reduces the 16 warp results independently
        unsigned long long v = (lane < FPS_T / 32) ? redw[par][lane] : 0ull;
        const unsigned hv = (unsigned)(v >> 32);
        const unsigned lv = (unsigned)v;
        const unsigned gmv = __reduce_max_sync(0xffffffffu, hv);
        const unsigned ii = (hv == gmv) ? lv : 0x7fffffffu;
        const int best = (int)__reduce_min_sync(0xffffffffu, ii);

        lx = pts[best * 3 + 0];
        ly = pts[best * 3 + 1];
        lz = pts[best * 3 + 2];
        if (t == 0) {
            float* o = new_xyz + ((size_t)b * NPOINT + iter) * 3;
            o[0] = lx; o[1] = ly; o[2] = lz;
        }
    }
}

// ---------------------------------------------------------------------------
// Kernel 2: ball query. One warp per center. Collects the first NSAMPLE
// point indices (ascending) with d2 < R2, padded with the first found index.
// ---------------------------------------------------------------------------
__global__ void __launch_bounds__(256)
ball_kernel(const float* __restrict__ points, const float* __restrict__ new_xyz,
            int* __restrict__ out_idx)
{
    const int gw = (blockIdx.x * blockDim.x + threadIdx.x) >> 5;
    const int lane = threadIdx.x & 31;
    if (gw >= BATCH * NPOINT) return;
    const int b = gw / NPOINT;
    const float* P = points + (size_t)b * NPTS * 3;

    const float cx = new_xyz[gw * 3 + 0];
    const float cy = new_xyz[gw * 3 + 1];
    const float cz = new_xyz[gw * 3 + 2];
    int* row = out_idx + (size_t)gw * NSAMPLE;

    int filled = 0;
    int first = 0;
    for (int basei = 0; basei < NPTS; basei += 32) {
        const int i = basei + lane;
        float x = P[i * 3 + 0], y = P[i * 3 + 1], z = P[i * 3 + 2];
        float dx = __fadd_rn(x, -cx);
        float dy = __fadd_rn(y, -cy);
        float dz = __fadd_rn(z, -cz);
        float d2 = __fadd_rn(__fadd_rn(__fmul_rn(dx, dx), __fmul_rn(dy, dy)),
                             __fmul_rn(dz, dz));
        unsigned m = __ballot_sync(0xffffffffu, d2 < R2);
        if (filled == 0 && m) first = basei + __ffs(m) - 1;
        if (d2 < R2) {
            int pos = filled + __popc(m & ((1u << lane) - 1));
            if (pos < NSAMPLE) row[pos] = i;
        }
        filled += __popc(m);
        if (filled >= NSAMPLE) break;
    }
    for (int j = filled + lane; j < NSAMPLE; j += 32) row[j] = first;
}

// ---------------------------------------------------------------------------
// Kernel 3: fused gather + pointwise conv.
// conv[b,p,o] = sum_{s,c} g[b,p,s,c] * w[o,c,s], k = c*32+s (matches W layout).
// Block = 64 points x 128 outputs, K streamed in 4-channel (128-k) chunks
// through SMEM. Thread: og = t%32 -> o in {og, og+32, og+64, og+96};
// pg = t/32 -> 8 points. 32 accumulators/thread.
// ---------------------------------------------------------------------------
#define PT 64

__global__ void __launch_bounds__(256, 1)
conv_kernel(const float* __restrict__ points,
            const float* __restrict__ features,
            const float* __restrict__ weight,
            const float* __restrict__ new_xyz,
            const int* __restrict__ ball_idx,
            float* __restrict__ conv_out)
{
    extern __shared__ char smraw[];
    float* s_g   = (float*)smraw;              // [64][128]
    float* s_w   = s_g + PT * 128;             // [128][129] padded
    int*   s_idx = (int*)(s_w + COUT * 129);   // [64][32]
    float* s_ctr = (float*)(s_idx + PT * NSAMPLE); // [64][3]

    const int t = threadIdx.x;
    const int b  = blockIdx.x >> 5;            // NPOINT/PT = 32 tiles per batch
    const int p0 = (blockIdx.x & 31) * PT;
    const float* P = points   + (size_t)b * NPTS * 3;
    const float* F = features + (size_t)b * NPTS * 64;

    for (int i = t; i < PT * NSAMPLE; i += 256)
        s_idx[i] = ball_idx[((size_t)b * NPOINT + p0) * NSAMPLE + i];
    for (int i = t; i < PT * 3; i += 256)
        s_ctr[i] = new_xyz[((size_t)b * NPOINT + p0) * 3 + i];
    __syncthreads();

    int myidx[8];
#pragma unroll
    for (int q = 0; q < 8; q++) myidx[q] = s_idx[q * 256 + t];

    const int og = t & 31;
    const int pg = t >> 5;
    float acc[8][4];
#pragma unroll
    for (int i = 0; i < 8; i++)
#pragma unroll
        for (int j = 0; j < 4; j++) acc[i][j] = 0.0f;

    for (int chunk = 0; chunk < 17; chunk++) {
        const int c0 = chunk * 4;
        const int nc = (chunk == 16) ? 3 : 4;
        __syncthreads();   // previous compute done before overwrite

        // stage g tile: 64p x 32s pairs, transposed to [p][ci*32 + s]
#pragma unroll
        for (int q = 0; q < 8; q++) {
            const int pr = q * 256 + t;
            const int p = pr >> 5, s = pr & 31;
            const int idx = myidx[q];
#pragma unroll
            for (int ci = 0; ci < 4; ci++) {
                const int c = c0 + ci;
                if (c >= CIN) break;
                float v;
                if (c < 3) v = P[idx * 3 + c] - s_ctr[p * 3 + c];
                else       v = F[idx * 64 + (c - 3)];
                s_g[p * 128 + ci * 32 + s] = v;
            }
        }
        // stage W tile: 128 o x up to 128 k, vectorized along k
        const int kend = nc * 32;
#pragma unroll
        for (int q = 0; q < 16; q++) {
            const int task = q * 256 + t;
            const int o = task >> 5;
            const int k4 = (task & 31) * 4;
            if (k4 < kend) {
                float4 wv = *(const float4*)(weight + (size_t)o * KTOT + c0 * 32 + k4);
                s_w[o * 129 + k4 + 0] = wv.x;
                s_w[o * 129 + k4 + 1] = wv.y;
                s_w[o * 129 + k4 + 2] = wv.z;
                s_w[o * 129 + k4 + 3] = wv.w;
            }
        }
        __syncthreads();

#pragma unroll 4
        for (int kk = 0; kk < kend; kk++) {
            const float w0 = s_w[(og +  0) * 129 + kk];
            const float w1 = s_w[(og + 32) * 129 + kk];
            const float w2 = s_w[(og + 64) * 129 + kk];
            const float w3 = s_w[(og + 96) * 129 + kk];
#pragma unroll
            for (int i = 0; i < 8; i++) {
                const float g = s_g[(pg * 8 + i) * 128 + kk];
                acc[i][0] = fmaf(g, w0, acc[i][0]);
                acc[i][1] = fmaf(g, w1, acc[i][1]);
                acc[i][2] = fmaf(g, w2, acc[i][2]);
                acc[i][3] = fmaf(g, w3, acc[i][3]);
            }
        }
    }

#pragma unroll
    for (int i = 0; i < 8; i++) {
        const int p = p0 + pg * 8 + i;
        float* dst = conv_out + ((size_t)b * NPOINT + p) * COUT;
        dst[og +  0] = acc[i][0];
        dst[og + 32] = acc[i][1];
        dst[og + 64] = acc[i][2];
        dst[og + 96] = acc[i][3];
    }
}

// ---------------------------------------------------------------------------

extern "C" void kernel_launch(void* const* d_in, const int* in_sizes, int n_in,
                              void* d_out, int out_size)
{
    const float* points   = (const float*)d_in[0];
    const float* features = (const float*)d_in[1];
    const float* weight   = (const float*)d_in[2];
    float* out = (float*)d_out;
    float* new_xyz = out;                            // B*NPOINT*3
    float* conv    = out + BATCH * NPOINT * 3;       // B*NPOINT*COUT

    const int fps_smem  = NPTS * 3 * sizeof(float);                       // 96 KB
    const int conv_smem = (PT * 128 + COUT * 129 + PT * 3) * sizeof(float)
                        + PT * NSAMPLE * sizeof(int);                     // ~106 KB

    cudaFuncSetAttribute(fps_kernel,  cudaFuncAttributeMaxDynamicSharedMemorySize, fps_smem);
    cudaFuncSetAttribute(conv_kernel, cudaFuncAttributeMaxDynamicSharedMemorySize, conv_smem);

    int* ball_ptr = nullptr;
    cudaGetSymbolAddress((void**)&ball_ptr, g_ball_idx);

    fps_kernel<<<BATCH, FPS_T, fps_smem>>>(points, new_xyz);
    ball_kernel<<<(BATCH * NPOINT) / 8, 256>>>(points, new_xyz, ball_ptr);
    conv_kernel<<<BATCH * (NPOINT / PT), 256, conv_smem>>>(
        points, features, weight, new_xyz, ball_ptr, conv);
}